// round 11
// baseline (speedup 1.0000x reference)
#include <cuda_runtime.h>
#include <math.h>

#define SPB       64
#define T_LEN     34
#define NTOK      (SPB * T_LEN)   // 2176
#define BTHREADS  256
#define CSTRIDE   35
#define VSTRIDE   36
#define WSTRIDE   36

__constant__ int c_flat[T_LEN] = {
    0,1,2,3,4,5,6,7,8,9, 11,
    0,1,2,3,4,5,6,7,8,9, 12,
    0,1,2,3,4,5,6,7,8,9, 10, 13
};

__device__ __forceinline__ float ex2f(float x) {
    float y;
    asm("ex2.approx.ftz.f32 %0, %1;" : "=f"(y) : "f"(x));
    return y;
}
__device__ __forceinline__ float rcpf(float x) {
    float y;
    asm("rcp.approx.ftz.f32 %0, %1;" : "=f"(y) : "f"(x));
    return y;
}
// gelu via A&S 7.1.26 erf (|err|<=1.5e-7)
__device__ __forceinline__ float gelu_fast(float z) {
    float a  = z * 0.70710678118654752f;
    float ax = fabsf(a);
    float t  = rcpf(fmaf(0.3275911f, ax, 1.0f));
    float p  = t * fmaf(t, fmaf(t, fmaf(t, fmaf(t, 1.061405429f, -1.453152027f),
                                        1.421413741f), -0.284496736f), 0.254829592f);
    float em = ex2f(-1.4426950408889634f * a * a);
    float er = fmaf(-p, em, 1.0f);
    er = copysignf(er, a);
    return 0.5f * z * (1.0f + er);
}

__global__ __launch_bounds__(BTHREADS, 5)
void micro_fused11(
    const int*   __restrict__ idx,
    const float* __restrict__ tokA,
    const float* __restrict__ tokStart,
    const float* __restrict__ tokStride,
    const float* __restrict__ z_hi,
    const float* __restrict__ specialEq,
    const float* __restrict__ qW,         // (4,3)
    const float* __restrict__ phase,
    const float* __restrict__ outA,       // (5,)
    const float* __restrict__ outB,       // (5,)
    const float* __restrict__ nw,         // (5,)
    const float* __restrict__ fc1,        // (2,5)
    const float* __restrict__ hp,         // (2,5)
    float*       __restrict__ out,        // (B,34,10)
    int B)
{
    __shared__ float  s_W   [T_LEN * WSTRIDE];   // e[t][s], sequence-independent
    __shared__ float  s_dinv[T_LEN];
    __shared__ float  s_r   [T_LEN];             // rmsnorm scalar: position-only!
    __shared__ float  s_vt  [SPB * VSTRIDE];     // per-token r_s * Vt(c)
    __shared__ unsigned char s_c[SPB * CSTRIDE]; // digits
    __shared__ float2 s_u   [NTOK + 2];          // (u0,u1); overlays s_mt/s_pt during build
    __shared__ float4 s_xc  [10];                // (x0, x1, Vt, -)
    __shared__ float4 s_xp  [T_LEN];             // (p0, p1, p2, |p|^2)
    __shared__ float  s_cB[5], s_hp[10], s_wf[10], s_wh[10];

    const int  tid       = threadIdx.x;
    const long base_tok  = (long)blockIdx.x * NTOK;
    const long total_tok = (long)B * T_LEN;

    float4* s_mt = reinterpret_cast<float4*>(s_u);          // [34]
    float4* s_pt = reinterpret_cast<float4*>(s_u) + T_LEN;  // [34]

    // ---- R0a: idx -> digit bytes ----
    #pragma unroll
    for (int r = 0; r < 9; ++r) {
        int li = tid + r * BTHREADS;
        if (li < NTOK) {
            int  yy = li / T_LEN;
            int  ss = li - yy * T_LEN;
            long g  = base_tok + li;
            int  v  = (g < total_tok) ? idx[g] : 0;
            s_c[yy * CSTRIDE + ss] = (unsigned char)v;
        }
    }
    // ---- R0b: parameter tables ----
    if (tid < 5)  s_cB[tid] = outB[tid];
    if (tid < 10) {
        s_hp[tid] = hp[tid];
        int cc = tid % 5;
        s_wf[tid] = nw[cc] * fc1[tid];
        s_wh[tid] = nw[cc] * hp[tid];
    }
    if (tid < T_LEN) {
        const int f = c_flat[tid];
        float p0, p1, p2;
        if (f < 10) {
            float a = 0.6283185307179586f * (float)f;
            p0 = 3.5f * __cosf(a);
            p1 = 3.5f * __sinf(a);
            p2 = 0.15f * (float)f;
        } else if (f == 10) {
            p0 = z_hi[0]; p1 = z_hi[1]; p2 = z_hi[2];
        } else if (f == 12) {
            p0 = specialEq[0]; p1 = specialEq[1]; p2 = specialEq[2];
        } else {
            p0 = p1 = p2 = 0.0f;
        }
        float pp = p0*p0 + p1*p1 + p2*p2;
        s_xp[tid] = make_float4(p0, p1, p2, pp);

        float amp = tokA[0];
        s_r[tid] = rsqrtf(fmaf(0.2f, fmaf(amp, amp, pp), 1e-5f));  // digit-independent!

        float pt0 = p0 * nw[2], pt1 = p1 * nw[3], pt2 = p2 * nw[4];
        s_pt[tid] = make_float4(pt0, pt1, pt2, 0.f);

        float q0 = qW[0]*pt0 + qW[1]*pt1 + qW[2]*pt2;
        float q1 = qW[3]*pt0 + qW[4]*pt1 + qW[5]*pt2;
        float q2 = qW[6]*pt0 + qW[7]*pt1 + qW[8]*pt2;
        float q3 = qW[9]*pt0 + qW[10]*pt1 + qW[11]*pt2;
        float cp = __cosf(phase[0]);
        float sp = __sinf(phase[0]);
        float r0  = q0*cp - q1*sp;
        float r1v = q0*sp + q1*cp;
        float r2v = q2*cp - q3*sp;
        float r3  = q2*sp + q3*cp;
        const float LG = 0.5f * 1.4426950408889634f;
        s_mt[tid] = make_float4(
            LG*(r0*qW[0] + r1v*qW[3] + r2v*qW[6] + r3*qW[9]),
            LG*(r0*qW[1] + r1v*qW[4] + r2v*qW[7] + r3*qW[10]),
            LG*(r0*qW[2] + r1v*qW[5] + r2v*qW[8] + r3*qW[11]), 0.f);
    }
    if (tid >= 64 && tid < 74) {
        const int c = tid - 64;
        float ang = tokStart[0] + (float)c * tokStride[0];
        float amp = tokA[0];
        float x0 = amp * __cosf(ang);
        float x1 = amp * __sinf(ang);
        float w0s = hp[0]*outA[0] + hp[1]*outA[1] + hp[2]*outA[2] + hp[3]*outA[3] + hp[4]*outA[4];
        float w1s = hp[5]*outA[0] + hp[6]*outA[1] + hp[7]*outA[2] + hp[8]*outA[3] + hp[9]*outA[4];
        float vt  = x0 * nw[0] * w0s + x1 * nw[1] * w1s;
        s_xc[c] = make_float4(x0, x1, vt, 0.f);
    }
    __syncthreads();

    // ---- R2a: e[t][s] table (595 entries, ONCE per block) ----
    for (int e = tid; e < 595; e += BTHREADS) {
        int t = (int)((sqrtf(fmaf(8.f, (float)e, 1.f)) - 1.f) * 0.5f);
        while ((t + 1) * (t + 2) / 2 <= e) ++t;
        while (t * (t + 1) / 2 > e) --t;
        int s = e - t * (t + 1) / 2;
        float4 m = s_mt[t];
        float4 p = s_pt[s];
        float g  = fmaf(m.x, p.x, fmaf(m.y, p.y, m.z * p.z));
        s_W[t * WSTRIDE + s] = ex2f((s_r[t] * s_r[s]) * g);
    }
    // ---- R2b: per-token vt = r_s * Vt(c) ----
    #pragma unroll 1
    for (int r = 0; r < 9; ++r) {
        int li = tid + r * BTHREADS;
        if (li < NTOK) {
            int yy = li / T_LEN;
            int ss = li - yy * T_LEN;
            int v  = (int)s_c[yy * CSTRIDE + ss];
            s_vt[yy * VSTRIDE + ss] = s_r[ss] * s_xc[v].z;
        }
    }
    __syncthreads();

    // ---- R3: softmax denominators (34 threads) ----
    if (tid < T_LEN) {
        const float* wr = s_W + tid * WSTRIDE;
        float den = 0.f;
        for (int s = 0; s <= tid; ++s) den += wr[s];
        s_dinv[tid] = rcpf(den);
    }
    __syncthreads();

    // ---- R4: attention (pure FMA) + fused epilogue ----
    #pragma unroll 1
    for (int r = 0; r < 9; ++r) {
        int it = tid + r * BTHREADS;
        if (it < NTOK) {
            const int t = it >> 6;              // warp-uniform
            const int y = it & 63;
            const float* __restrict__ wrow = s_W  + t * WSTRIDE;
            const float* __restrict__ vrow = s_vt + y * VSTRIDE;

            float acc = 0.f;
            int s = 0;
            for (; s + 4 <= t + 1; s += 4) {
                float4 w4 = *(const float4*)(wrow + s);   // broadcast
                float4 v4 = *(const float4*)(vrow + s);   // conflict-free .128
                acc = fmaf(w4.x, v4.x, acc);
                acc = fmaf(w4.y, v4.y, acc);
                acc = fmaf(w4.z, v4.z, acc);
                acc = fmaf(w4.w, v4.w, acc);
            }
            for (; s <= t; ++s) acc = fmaf(wrow[s], vrow[s], acc);
            const float dA = acc * s_dinv[t];

            const int c = (int)s_c[y * CSTRIDE + t];
            const float4 xc = s_xc[c];
            const float4 xp = s_xp[t];
            float X0 = fmaf(dA, s_cB[0], xc.x);
            float X1 = fmaf(dA, s_cB[1], xc.y);
            float X2 = fmaf(dA, s_cB[2], xp.x);
            float X3 = fmaf(dA, s_cB[3], xp.y);
            float X4 = fmaf(dA, s_cB[4], xp.z);

            float ss1 = fmaf(X0,X0, fmaf(X1,X1, fmaf(X2,X2, fmaf(X3,X3, X4*X4))));
            float r1  = rsqrtf(fmaf(0.2f, ss1, 1e-5f));
            float z0 = r1 * (X0*s_wf[0] + X1*s_wf[1] + X2*s_wf[2] + X3*s_wf[3] + X4*s_wf[4]);
            float z1 = r1 * (X0*s_wf[5] + X1*s_wf[6] + X2*s_wf[7] + X3*s_wf[8] + X4*s_wf[9]);
            float g0 = gelu_fast(z0);
            float g1 = gelu_fast(z1);
            float Y0 = X0 + g0*s_hp[0] + g1*s_hp[5];
            float Y1 = X1 + g0*s_hp[1] + g1*s_hp[6];
            float Y2 = X2 + g0*s_hp[2] + g1*s_hp[7];
            float Y3 = X3 + g0*s_hp[3] + g1*s_hp[8];
            float Y4 = X4 + g0*s_hp[4] + g1*s_hp[9];

            float ss2 = fmaf(Y0,Y0, fmaf(Y1,Y1, fmaf(Y2,Y2, fmaf(Y3,Y3, Y4*Y4))));
            float r2  = rsqrtf(fmaf(0.2f, ss2, 1e-5f));
            float u0 = r2 * (Y0*s_wh[0] + Y1*s_wh[1] + Y2*s_wh[2] + Y3*s_wh[3] + Y4*s_wh[4]);
            float u1 = r2 * (Y0*s_wh[5] + Y1*s_wh[6] + Y2*s_wh[7] + Y3*s_wh[8] + Y4*s_wh[9]);

            s_u[y * T_LEN + t] = make_float2(u0, u1);
        }
    }
    __syncthreads();

    // ---- R5: coalesced float4 output ----
    const long base_f  = base_tok * 10;
    const long total_f = total_tok * 10;
    float* __restrict__ ob = out + base_f;
    const int nf4 = (NTOK * 10) / 4;    // 5440

    for (int f4 = tid; f4 < nf4; f4 += BTHREADS) {
        const int el = f4 * 4;
        if (base_f + el + 4 <= total_f) {
            int tq = el / 10;
            int d  = el - tq * 10;
            float2 u = s_u[tq];
            float vv[4];
            #pragma unroll
            for (int k2 = 0; k2 < 4; ++k2) {
                float4 xc = s_xc[d];
                vv[k2] = fmaf(u.y, xc.y, u.x * xc.x);
                if (++d == 10) { d = 0; ++tq; u = s_u[tq]; }
            }
            reinterpret_cast<float4*>(ob)[f4] = make_float4(vv[0], vv[1], vv[2], vv[3]);
        }
    }
}

extern "C" void kernel_launch(void* const* d_in, const int* in_sizes, int n_in,
                              void* d_out, int out_size)
{
    const int B = in_sizes[0] / T_LEN;
    const int grid = (B + SPB - 1) / SPB;
    micro_fused11<<<grid, BTHREADS>>>(
        (const int*)d_in[0],
        (const float*)d_in[1],
        (const float*)d_in[2],
        (const float*)d_in[3],
        (const float*)d_in[4],
        (const float*)d_in[5],
        (const float*)d_in[6],
        (const float*)d_in[7],
        (const float*)d_in[8],
        (const float*)d_in[9],
        (const float*)d_in[10],
        (const float*)d_in[11],
        (const float*)d_in[12],
        (float*)d_out, B);
}

// round 12
// speedup vs baseline: 1.1732x; 1.1732x over previous
#include <cuda_runtime.h>
#include <math.h>

#define SPB       64
#define T_LEN     34
#define NTOK      (SPB * T_LEN)   // 2176
#define BTHREADS  128
#define CSTRIDE   35
#define DSTRIDE   35
#define WSTRIDE   36

__constant__ int c_flat[T_LEN] = {
    0,1,2,3,4,5,6,7,8,9, 11,
    0,1,2,3,4,5,6,7,8,9, 12,
    0,1,2,3,4,5,6,7,8,9, 10, 13
};

__device__ __forceinline__ float ex2f(float x) {
    float y;
    asm("ex2.approx.ftz.f32 %0, %1;" : "=f"(y) : "f"(x));
    return y;
}
__device__ __forceinline__ float rcpf(float x) {
    float y;
    asm("rcp.approx.ftz.f32 %0, %1;" : "=f"(y) : "f"(x));
    return y;
}
// gelu via A&S 7.1.26 erf (|err|<=1.5e-7)
__device__ __forceinline__ float gelu_fast(float z) {
    float a  = z * 0.70710678118654752f;
    float ax = fabsf(a);
    float t  = rcpf(fmaf(0.3275911f, ax, 1.0f));
    float p  = t * fmaf(t, fmaf(t, fmaf(t, fmaf(t, 1.061405429f, -1.453152027f),
                                        1.421413741f), -0.284496736f), 0.254829592f);
    float em = ex2f(-1.4426950408889634f * a * a);
    float er = fmaf(-p, em, 1.0f);
    er = copysignf(er, a);
    return 0.5f * z * (1.0f + er);
}

__global__ __launch_bounds__(BTHREADS, 8)
void micro_fused12(
    const int*   __restrict__ idx,
    const float* __restrict__ tokA,
    const float* __restrict__ tokStart,
    const float* __restrict__ tokStride,
    const float* __restrict__ z_hi,
    const float* __restrict__ specialEq,
    const float* __restrict__ qW,         // (4,3)
    const float* __restrict__ phase,
    const float* __restrict__ outA,       // (5,)
    const float* __restrict__ outB,       // (5,)
    const float* __restrict__ nw,         // (5,)
    const float* __restrict__ fc1,        // (2,5)
    const float* __restrict__ hp,         // (2,5)
    float*       __restrict__ out,        // (B,34,10)
    int B)
{
    __shared__ float  s_W   [T_LEN * WSTRIDE];       // E -> folded F
    __shared__ float  s_dA  [SPB * DSTRIDE];         // per-token dA
    __shared__ unsigned char s_c[SPB * CSTRIDE];     // digits
    // union region: [0,2240) = s_vt during build+inner; whole = s_u after
    __shared__ float  s_region[NTOK * 2 + 4];        // 4356+4 floats
    __shared__ float  s_r   [T_LEN];
    __shared__ float4 s_xc  [10];                    // (x0, x1, Vt, -)
    __shared__ float4 s_xp  [T_LEN];                 // (p0, p1, p2, |p|^2)
    __shared__ float  s_cB[5], s_hp[10], s_wf[10], s_wh[10];

    float*  s_vt = s_region;                                   // [SPB*35]
    float2* s_u  = reinterpret_cast<float2*>(s_region);        // [NTOK]
    float4* s_mt = reinterpret_cast<float4*>(s_region + 2240); // [34]
    float4* s_pt = s_mt + T_LEN;                               // [34]

    const int  tid       = threadIdx.x;
    const long base_tok  = (long)blockIdx.x * NTOK;
    const long total_tok = (long)B * T_LEN;

    // ---- P1: idx -> digits; parameter tables ----
    #pragma unroll
    for (int r = 0; r < 17; ++r) {
        int li = tid + r * BTHREADS;                 // 0..2175
        int  yy = li / T_LEN;
        int  ss = li - yy * T_LEN;
        long g  = base_tok + li;
        int  v  = (g < total_tok) ? idx[g] : 0;
        s_c[yy * CSTRIDE + ss] = (unsigned char)v;
    }
    if (tid < 5)  s_cB[tid] = outB[tid];
    if (tid < 10) {
        s_hp[tid] = hp[tid];
        int cc = tid % 5;
        s_wf[tid] = nw[cc] * fc1[tid];
        s_wh[tid] = nw[cc] * hp[tid];
    }
    if (tid >= 32 && tid < 32 + T_LEN) {
        const int t = tid - 32;
        const int f = c_flat[t];
        float p0, p1, p2;
        if (f < 10) {
            float a = 0.6283185307179586f * (float)f;
            p0 = 3.5f * __cosf(a);
            p1 = 3.5f * __sinf(a);
            p2 = 0.15f * (float)f;
        } else if (f == 10) {
            p0 = z_hi[0]; p1 = z_hi[1]; p2 = z_hi[2];
        } else if (f == 12) {
            p0 = specialEq[0]; p1 = specialEq[1]; p2 = specialEq[2];
        } else {
            p0 = p1 = p2 = 0.0f;
        }
        float pp = p0*p0 + p1*p1 + p2*p2;
        s_xp[t] = make_float4(p0, p1, p2, pp);

        float amp = tokA[0];
        s_r[t] = rsqrtf(fmaf(0.2f, fmaf(amp, amp, pp), 1e-5f));   // digit-independent

        float pt0 = p0 * nw[2], pt1 = p1 * nw[3], pt2 = p2 * nw[4];
        s_pt[t] = make_float4(pt0, pt1, pt2, 0.f);

        float q0 = qW[0]*pt0 + qW[1]*pt1 + qW[2]*pt2;
        float q1 = qW[3]*pt0 + qW[4]*pt1 + qW[5]*pt2;
        float q2 = qW[6]*pt0 + qW[7]*pt1 + qW[8]*pt2;
        float q3 = qW[9]*pt0 + qW[10]*pt1 + qW[11]*pt2;
        float cp = __cosf(phase[0]);
        float sp = __sinf(phase[0]);
        float r0  = q0*cp - q1*sp;
        float r1v = q0*sp + q1*cp;
        float r2v = q2*cp - q3*sp;
        float r3  = q2*sp + q3*cp;
        const float LG = 0.5f * 1.4426950408889634f;
        s_mt[t] = make_float4(
            LG*(r0*qW[0] + r1v*qW[3] + r2v*qW[6] + r3*qW[9]),
            LG*(r0*qW[1] + r1v*qW[4] + r2v*qW[7] + r3*qW[10]),
            LG*(r0*qW[2] + r1v*qW[5] + r2v*qW[8] + r3*qW[11]), 0.f);
    }
    if (tid >= 80 && tid < 90) {
        const int c = tid - 80;
        float ang = tokStart[0] + (float)c * tokStride[0];
        float amp = tokA[0];
        float x0 = amp * __cosf(ang);
        float x1 = amp * __sinf(ang);
        float w0s = hp[0]*outA[0] + hp[1]*outA[1] + hp[2]*outA[2] + hp[3]*outA[3] + hp[4]*outA[4];
        float w1s = hp[5]*outA[0] + hp[6]*outA[1] + hp[7]*outA[2] + hp[8]*outA[3] + hp[9]*outA[4];
        float vt  = x0 * nw[0] * w0s + x1 * nw[1] * w1s;
        s_xc[c] = make_float4(x0, x1, vt, 0.f);
    }
    __syncthreads();

    // ---- P2: W = E (rect iterate), vt = Vt(c) per token ----
    #pragma unroll 1
    for (int li = tid; li < T_LEN * T_LEN; li += BTHREADS) {
        int t = li / T_LEN;
        int s = li - t * T_LEN;
        if (s <= t) {
            float4 m = s_mt[t];
            float4 p = s_pt[s];
            float g  = fmaf(m.x, p.x, fmaf(m.y, p.y, m.z * p.z));
            s_W[t * WSTRIDE + s] = ex2f((s_r[t] * s_r[s]) * g);
        }
    }
    #pragma unroll 1
    for (int li = tid; li < NTOK; li += BTHREADS) {
        int yy = li / T_LEN;
        int ss = li - yy * T_LEN;
        s_vt[yy * CSTRIDE + ss] = s_xc[(int)s_c[yy * CSTRIDE + ss]].z;
    }
    __syncthreads();

    // ---- P3: dinv + fold F[t][s] = E * dinv[t] * r[s] ----
    if (tid < T_LEN) {
        float* wr = s_W + tid * WSTRIDE;
        float den = 0.f;
        for (int s = 0; s <= tid; ++s) den += wr[s];
        float dinv = rcpf(den);
        for (int s = 0; s <= tid; ++s) wr[s] *= dinv * s_r[s];
    }
    __syncthreads();

    // ---- P4: triangular matvec, thread-per-sequence, v in registers ----
    {
        const int role = tid >> 6;           // warps 0-1: t<24; warps 2-3: t>=24
        const int y    = tid & 63;
        const float* __restrict__ vrow = s_vt + y * CSTRIDE;
        float* __restrict__ darow = s_dA + y * DSTRIDE;

        if (role == 0) {
            float v[24];
            #pragma unroll
            for (int s = 0; s < 24; ++s) v[s] = vrow[s];
            #pragma unroll
            for (int t = 0; t < 24; ++t) {
                const float* __restrict__ w = s_W + t * WSTRIDE;
                float acc = 0.f;
                #pragma unroll
                for (int s = 0; s <= t; ++s) acc = fmaf(w[s], v[s], acc);
                darow[t] = acc;
            }
        } else {
            float v[T_LEN];
            #pragma unroll
            for (int s = 0; s < T_LEN; ++s) v[s] = vrow[s];
            #pragma unroll
            for (int t = 24; t < T_LEN; ++t) {
                const float* __restrict__ w = s_W + t * WSTRIDE;
                float acc = 0.f;
                #pragma unroll
                for (int s = 0; s <= t; ++s) acc = fmaf(w[s], v[s], acc);
                darow[t] = acc;
            }
        }
    }
    __syncthreads();

    // ---- P5: epilogue per token -> s_u (overwrites vt region; vt dead) ----
    #pragma unroll 1
    for (int r = 0; r < 17; ++r) {
        int it = tid + r * BTHREADS;          // 0..2175
        const int t = it >> 6;                // warp-uniform
        const int y = it & 63;
        const float dA = s_dA[y * DSTRIDE + t];
        const int c = (int)s_c[y * CSTRIDE + t];

        const float4 xc = s_xc[c];
        const float4 xp = s_xp[t];
        float X0 = fmaf(dA, s_cB[0], xc.x);
        float X1 = fmaf(dA, s_cB[1], xc.y);
        float X2 = fmaf(dA, s_cB[2], xp.x);
        float X3 = fmaf(dA, s_cB[3], xp.y);
        float X4 = fmaf(dA, s_cB[4], xp.z);

        float ss1 = fmaf(X0,X0, fmaf(X1,X1, fmaf(X2,X2, fmaf(X3,X3, X4*X4))));
        float r1  = rsqrtf(fmaf(0.2f, ss1, 1e-5f));
        float z0 = r1 * (X0*s_wf[0] + X1*s_wf[1] + X2*s_wf[2] + X3*s_wf[3] + X4*s_wf[4]);
        float z1 = r1 * (X0*s_wf[5] + X1*s_wf[6] + X2*s_wf[7] + X3*s_wf[8] + X4*s_wf[9]);
        float g0 = gelu_fast(z0);
        float g1 = gelu_fast(z1);
        float Y0 = X0 + g0*s_hp[0] + g1*s_hp[5];
        float Y1 = X1 + g0*s_hp[1] + g1*s_hp[6];
        float Y2 = X2 + g0*s_hp[2] + g1*s_hp[7];
        float Y3 = X3 + g0*s_hp[3] + g1*s_hp[8];
        float Y4 = X4 + g0*s_hp[4] + g1*s_hp[9];

        float ss2 = fmaf(Y0,Y0, fmaf(Y1,Y1, fmaf(Y2,Y2, fmaf(Y3,Y3, Y4*Y4))));
        float r2  = rsqrtf(fmaf(0.2f, ss2, 1e-5f));
        float u0 = r2 * (Y0*s_wh[0] + Y1*s_wh[1] + Y2*s_wh[2] + Y3*s_wh[3] + Y4*s_wh[4]);
        float u1 = r2 * (Y0*s_wh[5] + Y1*s_wh[6] + Y2*s_wh[7] + Y3*s_wh[8] + Y4*s_wh[9]);

        s_u[y * T_LEN + t] = make_float2(u0, u1);
    }
    __syncthreads();

    // ---- P6: coalesced float4 output ----
    const long base_f  = base_tok * 10;
    const long total_f = total_tok * 10;
    float* __restrict__ ob = out + base_f;
    const int nf4 = (NTOK * 10) / 4;          // 5440

    for (int f4 = tid; f4 < nf4; f4 += BTHREADS) {
        const int el = f4 * 4;
        if (base_f + el + 4 <= total_f) {
            int tq = el / 10;
            int d  = el - tq * 10;
            float2 u = s_u[tq];
            float vv[4];
            #pragma unroll
            for (int k2 = 0; k2 < 4; ++k2) {
                float4 xc = s_xc[d];
                vv[k2] = fmaf(u.y, xc.y, u.x * xc.x);
                if (++d == 10) { d = 0; ++tq; u = s_u[tq]; }
            }
            reinterpret_cast<float4*>(ob)[f4] = make_float4(vv[0], vv[1], vv[2], vv[3]);
        }
    }
}

extern "C" void kernel_launch(void* const* d_in, const int* in_sizes, int n_in,
                              void* d_out, int out_size)
{
    const int B = in_sizes[0] / T_LEN;
    const int grid = (B + SPB - 1) / SPB;
    micro_fused12<<<grid, BTHREADS>>>(
        (const int*)d_in[0],
        (const float*)d_in[1],
        (const float*)d_in[2],
        (const float*)d_in[3],
        (const float*)d_in[4],
        (const float*)d_in[5],
        (const float*)d_in[6],
        (const float*)d_in[7],
        (const float*)d_in[8],
        (const float*)d_in[9],
        (const float*)d_in[10],
        (const float*)d_in[11],
        (const float*)d_in[12],
        (float*)d_out, B);
}

// round 13
// speedup vs baseline: 1.1942x; 1.0179x over previous
#include <cuda_runtime.h>
#include <math.h>

#define SPB       64
#define T_LEN     34
#define NTOK      (SPB * T_LEN)   // 2176
#define BT        128
#define CSTRIDE   35
#define WSTRIDE   36

__constant__ int c_flat[T_LEN] = {
    0,1,2,3,4,5,6,7,8,9, 11,
    0,1,2,3,4,5,6,7,8,9, 12,
    0,1,2,3,4,5,6,7,8,9, 10, 13
};

// launch-constant tables (built once by setup_kernel)
__device__ float4 gF4[306];    // folded F, 34 rows x 36 floats
__device__ float4 gxc[10];     // (x0, x1, Vt, 0)
__device__ float4 gxp[T_LEN];  // (p0, p1, p2, 0)
__device__ float  gsc[40];     // cB[0..4], hp[5..14], wf[15..24], wh[25..34]

__device__ __forceinline__ float ex2f(float x) {
    float y;
    asm("ex2.approx.ftz.f32 %0, %1;" : "=f"(y) : "f"(x));
    return y;
}
__device__ __forceinline__ float rcpf(float x) {
    float y;
    asm("rcp.approx.ftz.f32 %0, %1;" : "=f"(y) : "f"(x));
    return y;
}
__device__ __forceinline__ float gelu_fast(float z) {
    float a  = z * 0.70710678118654752f;
    float ax = fabsf(a);
    float t  = rcpf(fmaf(0.3275911f, ax, 1.0f));
    float p  = t * fmaf(t, fmaf(t, fmaf(t, fmaf(t, 1.061405429f, -1.453152027f),
                                        1.421413741f), -0.284496736f), 0.254829592f);
    float em = ex2f(-1.4426950408889634f * a * a);
    float er = fmaf(-p, em, 1.0f);
    er = copysignf(er, a);
    return 0.5f * z * (1.0f + er);
}

__global__ void setup_kernel(
    const float* __restrict__ tokA, const float* __restrict__ tokStart,
    const float* __restrict__ tokStride, const float* __restrict__ z_hi,
    const float* __restrict__ specialEq, const float* __restrict__ qW,
    const float* __restrict__ phase, const float* __restrict__ outA,
    const float* __restrict__ outB, const float* __restrict__ nw,
    const float* __restrict__ fc1, const float* __restrict__ hp)
{
    __shared__ float4 s_mt[T_LEN], s_pt[T_LEN];
    __shared__ float  s_r [T_LEN];
    __shared__ float  s_W [T_LEN * WSTRIDE];
    const int tid = threadIdx.x;   // 128

    if (tid < T_LEN) {
        const int f = c_flat[tid];
        float p0, p1, p2;
        if (f < 10) {
            float a = 0.6283185307179586f * (float)f;
            p0 = 3.5f * __cosf(a);
            p1 = 3.5f * __sinf(a);
            p2 = 0.15f * (float)f;
        } else if (f == 10) {
            p0 = z_hi[0]; p1 = z_hi[1]; p2 = z_hi[2];
        } else if (f == 12) {
            p0 = specialEq[0]; p1 = specialEq[1]; p2 = specialEq[2];
        } else {
            p0 = p1 = p2 = 0.0f;
        }
        float pp = p0*p0 + p1*p1 + p2*p2;
        gxp[tid] = make_float4(p0, p1, p2, 0.f);

        float amp = tokA[0];
        s_r[tid] = rsqrtf(fmaf(0.2f, fmaf(amp, amp, pp), 1e-5f));

        float pt0 = p0 * nw[2], pt1 = p1 * nw[3], pt2 = p2 * nw[4];
        s_pt[tid] = make_float4(pt0, pt1, pt2, 0.f);

        float q0 = qW[0]*pt0 + qW[1]*pt1 + qW[2]*pt2;
        float q1 = qW[3]*pt0 + qW[4]*pt1 + qW[5]*pt2;
        float q2 = qW[6]*pt0 + qW[7]*pt1 + qW[8]*pt2;
        float q3 = qW[9]*pt0 + qW[10]*pt1 + qW[11]*pt2;
        float cp = __cosf(phase[0]);
        float sp = __sinf(phase[0]);
        float r0  = q0*cp - q1*sp;
        float r1v = q0*sp + q1*cp;
        float r2v = q2*cp - q3*sp;
        float r3  = q2*sp + q3*cp;
        const float LG = 0.5f * 1.4426950408889634f;
        s_mt[tid] = make_float4(
            LG*(r0*qW[0] + r1v*qW[3] + r2v*qW[6] + r3*qW[9]),
            LG*(r0*qW[1] + r1v*qW[4] + r2v*qW[7] + r3*qW[10]),
            LG*(r0*qW[2] + r1v*qW[5] + r2v*qW[8] + r3*qW[11]), 0.f);
    }
    if (tid >= 64 && tid < 74) {
        const int c = tid - 64;
        float ang = tokStart[0] + (float)c * tokStride[0];
        float amp = tokA[0];
        float x0 = amp * __cosf(ang);
        float x1 = amp * __sinf(ang);
        float w0s = hp[0]*outA[0] + hp[1]*outA[1] + hp[2]*outA[2] + hp[3]*outA[3] + hp[4]*outA[4];
        float w1s = hp[5]*outA[0] + hp[6]*outA[1] + hp[7]*outA[2] + hp[8]*outA[3] + hp[9]*outA[4];
        float vt  = x0 * nw[0] * w0s + x1 * nw[1] * w1s;
        gxc[c] = make_float4(x0, x1, vt, 0.f);
    }
    if (tid < 5)                 gsc[tid]          = outB[tid];
    if (tid >= 16 && tid < 26)   gsc[5  + tid-16]  = hp[tid-16];
    if (tid >= 32 && tid < 42) { int i = tid-32;   gsc[15 + i] = nw[i % 5] * fc1[i]; }
    if (tid >= 48 && tid < 58) { int i = tid-48;   gsc[25 + i] = nw[i % 5] * hp[i]; }
    __syncthreads();

    for (int li = tid; li < T_LEN * T_LEN; li += 128) {
        int t = li / T_LEN;
        int s = li - t * T_LEN;
        if (s <= t) {
            float4 m = s_mt[t];
            float4 p = s_pt[s];
            float g  = fmaf(m.x, p.x, fmaf(m.y, p.y, m.z * p.z));
            s_W[t * WSTRIDE + s] = ex2f((s_r[t] * s_r[s]) * g);
        }
    }
    __syncthreads();

    if (tid < T_LEN) {
        float* wr = s_W + tid * WSTRIDE;
        float den = 0.f;
        for (int s = 0; s <= tid; ++s) den += wr[s];
        float dinv = rcpf(den);
        for (int s = 0; s <= tid; ++s) wr[s] *= dinv * s_r[s];
        for (int s = tid + 1; s < WSTRIDE; ++s) wr[s] = 0.f;
    }
    __syncthreads();

    float* gFf = reinterpret_cast<float*>(gF4);
    for (int li = tid; li < T_LEN * WSTRIDE; li += 128) gFf[li] = s_W[li];
}

// triangular matvec for t in [T0,T1): dA[t] = sum_{s<=t} F[t][s] * v[s]
template<int T0, int T1>
__device__ __forceinline__ void matvec_seq(
    const unsigned char* __restrict__ crow,
    const float* __restrict__ sW,
    const float4* __restrict__ sxc,
    float* __restrict__ du)          // &s_u[y*T_LEN].x, stride 2 floats
{
    float v[T1];
    #pragma unroll
    for (int s = 0; s < T1; ++s) v[s] = sxc[(int)crow[s]].z;

    #pragma unroll
    for (int t = T0; t < T1; ++t) {
        const float* __restrict__ w = sW + t * WSTRIDE;
        float a0 = 0.f, a1 = 0.f;
        #pragma unroll
        for (int s = 0; s + 2 <= t + 1; s += 2) {
            a0 = fmaf(w[s],   v[s],   a0);
            a1 = fmaf(w[s+1], v[s+1], a1);
        }
        if ((t + 1) & 1) a0 = fmaf(w[t], v[t], a0);
        du[2 * t] = a0 + a1;
    }
}

__global__ __launch_bounds__(BT, 8)
void micro_fused13(const int* __restrict__ idx, float* __restrict__ out, int B)
{
    __shared__ float  s_W [T_LEN * WSTRIDE];     // 4.9 KB
    __shared__ unsigned char s_c[SPB * CSTRIDE]; // 2.24 KB
    __shared__ float2 s_u [NTOK];                // 17.4 KB: dA in .x -> (u0,u1)
    __shared__ float4 s_xc[10];
    __shared__ float4 s_xp[T_LEN];
    __shared__ float  s_sc[40];

    const int  tid       = threadIdx.x;
    const long base_tok  = (long)blockIdx.x * NTOK;
    const long total_tok = (long)B * T_LEN;

    // ---- P1: idx -> digits; constant tables from global ----
    #pragma unroll
    for (int r = 0; r < 17; ++r) {
        int li = tid + r * BT;                   // 0..2175
        int  yy = li / T_LEN;
        int  ss = li - yy * T_LEN;
        long g  = base_tok + li;
        int  v  = (g < total_tok) ? idx[g] : 0;
        s_c[yy * CSTRIDE + ss] = (unsigned char)v;
    }
    #pragma unroll
    for (int r = 0; r < 3; ++r) {
        int li = tid + r * BT;
        if (li < 306) reinterpret_cast<float4*>(s_W)[li] = gF4[li];
    }
    if (tid < 40)                s_sc[tid]      = gsc[tid];
    if (tid >= 48 && tid < 58)   s_xc[tid - 48] = gxc[tid - 48];
    if (tid >= 64 && tid < 64 + T_LEN) s_xp[tid - 64] = gxp[tid - 64];
    __syncthreads();

    const float* s_cB = s_sc;
    const float* s_hp = s_sc + 5;
    const float* s_wf = s_sc + 15;
    const float* s_wh = s_sc + 25;

    // ---- P2: triangular matvec, thread-per-sequence, dA -> s_u[..].x ----
    {
        const int role = tid >> 6;
        const int y    = tid & 63;
        const unsigned char* __restrict__ crow = s_c + y * CSTRIDE;
        float* __restrict__ du = reinterpret_cast<float*>(s_u + y * T_LEN);
        if (role == 0) matvec_seq<0, 24>(crow, s_W, s_xc, du);
        else           matvec_seq<24, T_LEN>(crow, s_W, s_xc, du);
    }
    __syncthreads();

    // ---- P3: epilogue per token, in-place s_u: dA -> (u0,u1) ----
    #pragma unroll 1
    for (int r = 0; r < 17; ++r) {
        int it = tid + r * BT;                   // 0..2175
        const int t = it >> 6;                   // warp-uniform
        const int y = it & 63;
        const int tok = y * T_LEN + t;
        const float dA = s_u[tok].x;
        const int c = (int)s_c[y * CSTRIDE + t];

        const float4 xc = s_xc[c];
        const float4 xp = s_xp[t];
        float X0 = fmaf(dA, s_cB[0], xc.x);
        float X1 = fmaf(dA, s_cB[1], xc.y);
        float X2 = fmaf(dA, s_cB[2], xp.x);
        float X3 = fmaf(dA, s_cB[3], xp.y);
        float X4 = fmaf(dA, s_cB[4], xp.z);

        float ss1 = fmaf(X0,X0, fmaf(X1,X1, fmaf(X2,X2, fmaf(X3,X3, X4*X4))));
        float r1  = rsqrtf(fmaf(0.2f, ss1, 1e-5f));
        float z0 = r1 * (X0*s_wf[0] + X1*s_wf[1] + X2*s_wf[2] + X3*s_wf[3] + X4*s_wf[4]);
        float z1 = r1 * (X0*s_wf[5] + X1*s_wf[6] + X2*s_wf[7] + X3*s_wf[8] + X4*s_wf[9]);
        float g0 = gelu_fast(z0);
        float g1 = gelu_fast(z1);
        float Y0 = X0 + g0*s_hp[0] + g1*s_hp[5];
        float Y1 = X1 + g0*s_hp[1] + g1*s_hp[6];
        float Y2 = X2 + g0*s_hp[2] + g1*s_hp[7];
        float Y3 = X3 + g0*s_hp[3] + g1*s_hp[8];
        float Y4 = X4 + g0*s_hp[4] + g1*s_hp[9];

        float ss2 = fmaf(Y0,Y0, fmaf(Y1,Y1, fmaf(Y2,Y2, fmaf(Y3,Y3, Y4*Y4))));
        float r2  = rsqrtf(fmaf(0.2f, ss2, 1e-5f));
        float u0 = r2 * (Y0*s_wh[0] + Y1*s_wh[1] + Y2*s_wh[2] + Y3*s_wh[3] + Y4*s_wh[4]);
        float u1 = r2 * (Y0*s_wh[5] + Y1*s_wh[6] + Y2*s_wh[7] + Y3*s_wh[8] + Y4*s_wh[9]);

        s_u[tok] = make_float2(u0, u1);
    }
    __syncthreads();

    // ---- P4: coalesced float4 output ----
    const long base_f  = base_tok * 10;
    const long total_f = total_tok * 10;
    float* __restrict__ ob = out + base_f;
    const int nf4 = (NTOK * 10) / 4;             // 5440

    for (int f4 = tid; f4 < nf4; f4 += BT) {
        const int el = f4 * 4;
        if (base_f + el + 4 <= total_f) {
            int tq = el / 10;
            int d  = el - tq * 10;
            float2 u = s_u[tq];
            float vv[4];
            #pragma unroll
            for (int k2 = 0; k2 < 4; ++k2) {
                float4 xc = s_xc[d];
                vv[k2] = fmaf(u.y, xc.y, u.x * xc.x);
                if (++d == 10) { d = 0; ++tq; u = s_u[tq]; }
            }
            reinterpret_cast<float4*>(ob)[f4] = make_float4(vv[0], vv[1], vv[2], vv[3]);
        }
    }
}

extern "C" void kernel_launch(void* const* d_in, const int* in_sizes, int n_in,
                              void* d_out, int out_size)
{
    const int B = in_sizes[0] / T_LEN;
    const int grid = (B + SPB - 1) / SPB;

    setup_kernel<<<1, 128>>>(
        (const float*)d_in[1],  (const float*)d_in[2],
        (const float*)d_in[3],  (const float*)d_in[4],
        (const float*)d_in[5],  (const float*)d_in[6],
        (const float*)d_in[7],  (const float*)d_in[8],
        (const float*)d_in[9],  (const float*)d_in[10],
        (const float*)d_in[11], (const float*)d_in[12]);

    micro_fused13<<<grid, BT>>>((const int*)d_in[0], (float*)d_out, B);
}

// round 15
// speedup vs baseline: 1.3030x; 1.0911x over previous
#include <cuda_runtime.h>
#include <math.h>

#define SPB       64
#define T_LEN     34
#define NTOK      (SPB * T_LEN)   // 2176
#define BT        128
#define CSTRIDE   35
#define WSTRIDE   36

__constant__ int c_flat[T_LEN] = {
    0,1,2,3,4,5,6,7,8,9, 11,
    0,1,2,3,4,5,6,7,8,9, 12,
    0,1,2,3,4,5,6,7,8,9, 10, 13
};

__device__ __forceinline__ float ex2f(float x) {
    float y;
    asm("ex2.approx.ftz.f32 %0, %1;" : "=f"(y) : "f"(x));
    return y;
}
__device__ __forceinline__ float rcpf(float x) {
    float y;
    asm("rcp.approx.ftz.f32 %0, %1;" : "=f"(y) : "f"(x));
    return y;
}
__device__ __forceinline__ float gelu_fast(float z) {
    float a  = z * 0.70710678118654752f;
    float ax = fabsf(a);
    float t  = rcpf(fmaf(0.3275911f, ax, 1.0f));
    float p  = t * fmaf(t, fmaf(t, fmaf(t, fmaf(t, 1.061405429f, -1.453152027f),
                                        1.421413741f), -0.284496736f), 0.254829592f);
    float em = ex2f(-1.4426950408889634f * a * a);
    float er = fmaf(-p, em, 1.0f);
    er = copysignf(er, a);
    return 0.5f * z * (1.0f + er);
}

// triangular matvec for t in [T0,T1): dA[t] = sum_{s<=t} F[t][s]*v[s]
// W rows contiguous & 16B-aligned -> float4 broadcast loads.
template<int T0, int T1>
__device__ __forceinline__ void matvec_seq(
    const unsigned char* __restrict__ crow,
    const float* __restrict__ sW,
    const float4* __restrict__ sxc,
    float* __restrict__ du)          // &s_u[y*T_LEN].x, stride 2 floats
{
    float v[T1];
    #pragma unroll
    for (int s = 0; s < T1; ++s) v[s] = sxc[(int)crow[s]].z;

    #pragma unroll
    for (int t = T0; t < T1; ++t) {
        const float* __restrict__ w = sW + t * WSTRIDE;
        float a0 = 0.f, a1 = 0.f;
        const int nf = ((t + 1) >> 2) << 2;
        #pragma unroll
        for (int s = 0; s < nf; s += 4) {
            float4 w4 = *(const float4*)(w + s);
            a0 = fmaf(w4.x, v[s],   a0);
            a1 = fmaf(w4.y, v[s+1], a1);
            a0 = fmaf(w4.z, v[s+2], a0);
            a1 = fmaf(w4.w, v[s+3], a1);
        }
        #pragma unroll
        for (int s = nf; s <= t; ++s) a0 = fmaf(w[s], v[s], a0);
        du[2 * t] = a0 + a1;
    }
}

__global__ __launch_bounds__(BT, 8)
void micro_fused15(
    const int*   __restrict__ idx,
    const float* __restrict__ tokA,
    const float* __restrict__ tokStart,
    const float* __restrict__ tokStride,
    const float* __restrict__ z_hi,
    const float* __restrict__ specialEq,
    const float* __restrict__ qW,         // (4,3)
    const float* __restrict__ phase,
    const float* __restrict__ outA,       // (5,)
    const float* __restrict__ outB,       // (5,)
    const float* __restrict__ nw,         // (5,)
    const float* __restrict__ fc1,        // (2,5)
    const float* __restrict__ hp,         // (2,5)
    float*       __restrict__ out,        // (B,34,10)
    int B)
{
    __shared__ float  s_W [T_LEN * WSTRIDE];     // E -> folded F (4.9 KB)
    __shared__ unsigned char s_c[SPB * CSTRIDE]; // digits (2.2 KB)
    __shared__ float2 s_u [NTOK];                // dA in .x -> (u0,u1) (17.4 KB)
    __shared__ float4 s_xc[10];                  // (x0,x1,Vt,0)
    __shared__ float4 s_xp[T_LEN];               // (p0,p1,p2,0)
    __shared__ float  s_r [T_LEN];
    __shared__ float  s_dinv[T_LEN];
    __shared__ float  s_sc[40];                  // cB[0..4], hp[5..14], wf[15..24], wh[25..34]

    // build-time overlays on s_u (dead until matvec writes)
    float4* s_mt = reinterpret_cast<float4*>(s_u);          // [34]
    float4* s_pt = reinterpret_cast<float4*>(s_u) + T_LEN;  // [34]

    const int  tid       = threadIdx.x;
    const long base_tok  = (long)blockIdx.x * NTOK;
    const long total_tok = (long)B * T_LEN;

    // ---- P1: idx -> digits; parameter tables ----
    #pragma unroll
    for (int r = 0; r < 17; ++r) {
        int li = tid + r * BT;                   // 0..2175
        int  yy = li / T_LEN;
        int  ss = li - yy * T_LEN;
        long g  = base_tok + li;
        int  v  = (g < total_tok) ? idx[g] : 0;
        s_c[yy * CSTRIDE + ss] = (unsigned char)v;
    }
    if (tid < 40) {                              // scalar params: ALL 35 entries covered
        int i = tid;
        float v = 0.f;
        if (i < 5)       v = outB[i];
        else if (i < 15) v = hp[i - 5];
        else if (i < 25) v = nw[(i - 15) % 5] * fc1[i - 15];
        else if (i < 35) v = nw[(i - 25) % 5] * hp[i - 25];
        s_sc[i] = v;
    }
    if (tid >= 64 && tid < 64 + T_LEN) {         // warp 2-3: positions
        const int t = tid - 64;
        const int f = c_flat[t];
        float p0, p1, p2;
        if (f < 10) {
            float a = 0.6283185307179586f * (float)f;
            p0 = 3.5f * __cosf(a);
            p1 = 3.5f * __sinf(a);
            p2 = 0.15f * (float)f;
        } else if (f == 10) {
            p0 = z_hi[0]; p1 = z_hi[1]; p2 = z_hi[2];
        } else if (f == 12) {
            p0 = specialEq[0]; p1 = specialEq[1]; p2 = specialEq[2];
        } else {
            p0 = p1 = p2 = 0.0f;
        }
        float pp = p0*p0 + p1*p1 + p2*p2;
        s_xp[t] = make_float4(p0, p1, p2, 0.f);

        float amp = tokA[0];
        s_r[t] = rsqrtf(fmaf(0.2f, fmaf(amp, amp, pp), 1e-5f));

        float pt0 = p0 * nw[2], pt1 = p1 * nw[3], pt2 = p2 * nw[4];
        s_pt[t] = make_float4(pt0, pt1, pt2, 0.f);

        float q0 = qW[0]*pt0 + qW[1]*pt1 + qW[2]*pt2;
        float q1 = qW[3]*pt0 + qW[4]*pt1 + qW[5]*pt2;
        float q2 = qW[6]*pt0 + qW[7]*pt1 + qW[8]*pt2;
        float q3 = qW[9]*pt0 + qW[10]*pt1 + qW[11]*pt2;
        float cp = __cosf(phase[0]);
        float sp = __sinf(phase[0]);
        float r0  = q0*cp - q1*sp;
        float r1v = q0*sp + q1*cp;
        float r2v = q2*cp - q3*sp;
        float r3  = q2*sp + q3*cp;
        const float LG = 0.5f * 1.4426950408889634f;
        s_mt[t] = make_float4(
            LG*(r0*qW[0] + r1v*qW[3] + r2v*qW[6] + r3*qW[9]),
            LG*(r0*qW[1] + r1v*qW[4] + r2v*qW[7] + r3*qW[10]),
            LG*(r0*qW[2] + r1v*qW[5] + r2v*qW[8] + r3*qW[11]), 0.f);
    }
    if (tid >= 48 && tid < 58) {                 // warp 1: digit table
        const int c = tid - 48;
        float ang = tokStart[0] + (float)c * tokStride[0];
        float amp = tokA[0];
        float x0 = amp * __cosf(ang);
        float x1 = amp * __sinf(ang);
        float w0s = hp[0]*outA[0] + hp[1]*outA[1] + hp[2]*outA[2] + hp[3]*outA[3] + hp[4]*outA[4];
        float w1s = hp[5]*outA[0] + hp[6]*outA[1] + hp[7]*outA[2] + hp[8]*outA[3] + hp[9]*outA[4];
        float vt  = x0 * nw[0] * w0s + x1 * nw[1] * w1s;
        s_xc[c] = make_float4(x0, x1, vt, 0.f);
    }
    __syncthreads();

    // ---- P2: E[t][s] = exp2(r_t r_s g(t,s)) ----
    #pragma unroll 1
    for (int li = tid; li < T_LEN * T_LEN; li += BT) {
        int t = li / T_LEN;
        int s = li - t * T_LEN;
        if (s <= t) {
            float4 m = s_mt[t];
            float4 p = s_pt[s];
            float g  = fmaf(m.x, p.x, fmaf(m.y, p.y, m.z * p.z));
            s_W[t * WSTRIDE + s] = ex2f((s_r[t] * s_r[s]) * g);
        }
    }
    __syncthreads();

    // ---- P3a: row denominators (float4 sums, 34 threads) ----
    if (tid < T_LEN) {
        const float* wr = s_W + tid * WSTRIDE;
        float d0 = 0.f, d1 = 0.f;
        const int nf = ((tid + 1) >> 2) << 2;
        for (int s = 0; s < nf; s += 4) {
            float4 w4 = *(const float4*)(wr + s);
            d0 += w4.x + w4.z;
            d1 += w4.y + w4.w;
        }
        for (int s = nf; s <= tid; ++s) d0 += wr[s];
        s_dinv[tid] = rcpf(d0 + d1);
    }
    __syncthreads();

    // ---- P3b: fold F = E * dinv[t] * r[s] (rect-parallel) ----
    #pragma unroll 1
    for (int li = tid; li < T_LEN * T_LEN; li += BT) {
        int t = li / T_LEN;
        int s = li - t * T_LEN;
        if (s <= t) s_W[t * WSTRIDE + s] *= s_dinv[t] * s_r[s];
    }
    __syncthreads();

    // ---- P4: triangular matvec, thread-per-sequence, dA -> s_u[..].x ----
    {
        const int role = tid >> 6;
        const int y    = tid & 63;
        const unsigned char* __restrict__ crow = s_c + y * CSTRIDE;
        float* __restrict__ du = reinterpret_cast<float*>(s_u + y * T_LEN);
        if (role == 0) matvec_seq<0, 24>(crow, s_W, s_xc, du);
        else           matvec_seq<24, T_LEN>(crow, s_W, s_xc, du);
    }
    __syncthreads();

    const float* s_cB = s_sc;
    const float* s_hp = s_sc + 5;
    const float* s_wf = s_sc + 15;
    const float* s_wh = s_sc + 25;

    // ---- P5: epilogue per token, in-place s_u: dA -> (u0,u1) ----
    #pragma unroll 1
    for (int r = 0; r < 17; ++r) {
        int it = tid + r * BT;                   // 0..2175
        const int t = it >> 6;                   // warp-uniform
        const int y = it & 63;
        const int tok = y * T_LEN + t;
        const float dA = s_u[tok].x;
        const int c = (int)s_c[y * CSTRIDE + t];

        const float4 xc = s_xc[c];
        const float4 xp = s_xp[t];
        float X0 = fmaf(dA, s_cB[0], xc.x);
        float X1 = fmaf(dA, s_cB[1], xc.y);
        float X2 = fmaf(dA, s_cB[2], xp.x);
        float X3 = fmaf(dA, s_cB[3], xp.y);
        float X4 = fmaf(dA, s_cB[4], xp.z);

        float ss1 = fmaf(X0,X0, fmaf(X1,X1, fmaf(X2,X2, fmaf(X3,X3, X4*X4))));
        float r1  = rsqrtf(fmaf(0.2f, ss1, 1e-5f));
        float z0 = r1 * (X0*s_wf[0] + X1*s_wf[1] + X2*s_wf[2] + X3*s_wf[3] + X4*s_wf[4]);
        float z1 = r1 * (X0*s_wf[5] + X1*s_wf[6] + X2*s_wf[7] + X3*s_wf[8] + X4*s_wf[9]);
        float g0 = gelu_fast(z0);
        float g1 = gelu_fast(z1);
        float Y0 = X0 + g0*s_hp[0] + g1*s_hp[5];
        float Y1 = X1 + g0*s_hp[1] + g1*s_hp[6];
        float Y2 = X2 + g0*s_hp[2] + g1*s_hp[7];
        float Y3 = X3 + g0*s_hp[3] + g1*s_hp[8];
        float Y4 = X4 + g0*s_hp[4] + g1*s_hp[9];

        float ss2 = fmaf(Y0,Y0, fmaf(Y1,Y1, fmaf(Y2,Y2, fmaf(Y3,Y3, Y4*Y4))));
        float r2  = rsqrtf(fmaf(0.2f, ss2, 1e-5f));
        float u0 = r2 * (Y0*s_wh[0] + Y1*s_wh[1] + Y2*s_wh[2] + Y3*s_wh[3] + Y4*s_wh[4]);
        float u1 = r2 * (Y0*s_wh[5] + Y1*s_wh[6] + Y2*s_wh[7] + Y3*s_wh[8] + Y4*s_wh[9]);

        s_u[tok] = make_float2(u0, u1);
    }
    __syncthreads();

    // ---- P6: coalesced float4 output ----
    const long base_f  = base_tok * 10;
    const long total_f = total_tok * 10;
    float* __restrict__ ob = out + base_f;
    const int nf4 = (NTOK * 10) / 4;             // 5440

    for (int f4 = tid; f4 < nf4; f4 += BT) {
        const int el = f4 * 4;
        if (base_f + el + 4 <= total_f) {
            int tq = el / 10;
            int d  = el - tq * 10;
            float2 u = s_u[tq];
            float vv[4];
            #pragma unroll
            for (int k2 = 0; k2 < 4; ++k2) {
                float4 xc = s_xc[d];
                vv[k2] = fmaf(u.y, xc.y, u.x * xc.x);
                if (++d == 10) { d = 0; ++tq; u = s_u[tq]; }
            }
            reinterpret_cast<float4*>(ob)[f4] = make_float4(vv[0], vv[1], vv[2], vv[3]);
        }
    }
}

extern "C" void kernel_launch(void* const* d_in, const int* in_sizes, int n_in,
                              void* d_out, int out_size)
{
    const int B = in_sizes[0] / T_LEN;
    const int grid = (B + SPB - 1) / SPB;
    micro_fused15<<<grid, BT>>>(
        (const int*)d_in[0],
        (const float*)d_in[1],
        (const float*)d_in[2],
        (const float*)d_in[3],
        (const float*)d_in[4],
        (const float*)d_in[5],
        (const float*)d_in[6],
        (const float*)d_in[7],
        (const float*)d_in[8],
        (const float*)d_in[9],
        (const float*)d_in[10],
        (const float*)d_in[11],
        (const float*)d_in[12],
        (float*)d_out, B);
}